// round 3
// baseline (speedup 1.0000x reference)
#include <cuda_runtime.h>

#define N_NODES 100000
#define DIM     128
#define NE      600000
#define NEC     200000
#define NDEPTH  4

// ---------------- scratch (static device globals; no allocation) ----------------
__device__ float g_xw1[N_NODES * DIM];
__device__ float g_xw2[N_NODES * DIM];
__device__ float g_xa [N_NODES * DIM];
__device__ float g_xb [N_NODES * DIM];
__device__ float g_dinv1[N_NODES];
__device__ float g_dinv2[N_NODES];
__device__ float g_norm1[NE];
__device__ float g_norm2[NEC];
__device__ int   g_src1[NE],  g_dst1[NE];
__device__ int   g_src2[NEC], g_dst2[NEC];
__device__ int   g_is64;

// ---------------- dtype autodetect: int64 edges have all-zero high words ----------------
__global__ void detect_kernel(const unsigned int* __restrict__ ebuf, int cnt) {
    __shared__ unsigned int acc;
    if (threadIdx.x == 0) acc = 0u;
    __syncthreads();
    unsigned int v = 0u;
    for (int i = threadIdx.x; i < cnt; i += blockDim.x) v |= ebuf[2 * i + 1];
    atomicOr(&acc, v);
    __syncthreads();
    if (threadIdx.x == 0) g_is64 = (acc == 0u) ? 1 : 0;
}

__global__ void decode_kernel(const void* __restrict__ ebuf,
                              int* __restrict__ src, int* __restrict__ dst, int E) {
    int i = blockIdx.x * blockDim.x + threadIdx.x;
    if (i >= E) return;
    if (g_is64) {
        const long long* p = (const long long*)ebuf;
        src[i] = (int)p[i];
        dst[i] = (int)p[E + i];
    } else {
        const int* p = (const int*)ebuf;
        src[i] = p[i];
        dst[i] = p[E + i];
    }
}

// ---------------- degree / norm precompute (once per launch, reused all layers) ------
__global__ void init_deg_kernel(int n) {
    int i = blockIdx.x * blockDim.x + threadIdx.x;
    if (i < n) { g_dinv1[i] = 1.0f; g_dinv2[i] = 1.0f; }  // self-loop counts as 1
}

__global__ void count_deg_kernel(const int* __restrict__ dst, float* __restrict__ deg, int E) {
    int i = blockIdx.x * blockDim.x + threadIdx.x;
    if (i < E) atomicAdd(&deg[dst[i]], 1.0f);
}

__global__ void finish_dinv_kernel(int n) {
    int i = blockIdx.x * blockDim.x + threadIdx.x;
    if (i < n) {
        g_dinv1[i] = rsqrtf(g_dinv1[i]);
        g_dinv2[i] = rsqrtf(g_dinv2[i]);
    }
}

__global__ void compute_norm_kernel(const int* __restrict__ src, const int* __restrict__ dst,
                                    const float* __restrict__ dinv, float* __restrict__ norm, int E) {
    int i = blockIdx.x * blockDim.x + threadIdx.x;
    if (i < E) norm[i] = dinv[src[i]] * dinv[dst[i]];
}

// ---------------- dual GEMM: xw1 = relu?(x) @ W1, xw2 = relu?(x) @ W2 ----------------
// 128x128 C-tile per block, K=128 in 4 chunks of 32, 256 threads, 8x8 micro-tile.
template <int RELU>
__global__ void __launch_bounds__(256)
gemm_dual_kernel(const float* __restrict__ A,
                 const float* __restrict__ W1, const float* __restrict__ W2,
                 float* __restrict__ C1, float* __restrict__ C2, int n) {
    const float* W = blockIdx.y ? W2 : W1;
    float*       C = blockIdx.y ? C2 : C1;

    __shared__ float As[128][33];   // pad -> conflict-free column reads
    __shared__ float Bs[32][128];

    const int row0 = blockIdx.x * 128;
    const int tid  = threadIdx.x;
    const int tx   = tid & 15;      // 0..15  -> 8 cols each
    const int ty   = tid >> 4;      // 0..15  -> 8 rows each

    float acc[8][8];
#pragma unroll
    for (int i = 0; i < 8; i++)
#pragma unroll
        for (int j = 0; j < 8; j++) acc[i][j] = 0.0f;

#pragma unroll 1
    for (int kb = 0; kb < 128; kb += 32) {
        // A tile: 128 rows x 32 cols, coalesced scalar loads
#pragma unroll
        for (int l = 0; l < 16; l++) {
            int idx = tid + l * 256;          // 0..4095
            int r = idx >> 5, c = idx & 31;
            int row = row0 + r;
            float v = 0.0f;
            if (row < n) v = A[row * 128 + kb + c];
            if (RELU) v = fmaxf(v, 0.0f);
            As[r][c] = v;
        }
        // B tile: 32 x 128, float4 coalesced
#pragma unroll
        for (int l = 0; l < 4; l++) {
            int idx = tid + l * 256;          // 0..1023 (float4 units)
            int kr = idx >> 5, cc = (idx & 31) * 4;
            *(float4*)&Bs[kr][cc] = *(const float4*)&W[(kb + kr) * 128 + cc];
        }
        __syncthreads();

#pragma unroll 8
        for (int k = 0; k < 32; k++) {
            float a[8], b[8];
#pragma unroll
            for (int j = 0; j < 8; j++) a[j] = As[ty * 8 + j][k];
            float4 b0 = *(const float4*)&Bs[k][tx * 8];
            float4 b1 = *(const float4*)&Bs[k][tx * 8 + 4];
            b[0] = b0.x; b[1] = b0.y; b[2] = b0.z; b[3] = b0.w;
            b[4] = b1.x; b[5] = b1.y; b[6] = b1.z; b[7] = b1.w;
#pragma unroll
            for (int i = 0; i < 8; i++)
#pragma unroll
                for (int j = 0; j < 8; j++) acc[i][j] += a[i] * b[j];
        }
        __syncthreads();
    }

#pragma unroll
    for (int i = 0; i < 8; i++) {
        int row = row0 + ty * 8 + i;
        if (row < n) {
            *(float4*)&C[row * 128 + tx * 8]     = make_float4(acc[i][0], acc[i][1], acc[i][2], acc[i][3]);
            *(float4*)&C[row * 128 + tx * 8 + 4] = make_float4(acc[i][4], acc[i][5], acc[i][6], acc[i][7]);
    }
    }
}

// ---------------- out[v] = xw1[v]*dinv1^2 + xw2[v]*dinv2^2 + b1 + b2 (self-loops + bias)
__global__ void init_out_kernel(float* __restrict__ out,
                                const float* __restrict__ xw1, const float* __restrict__ xw2,
                                const float* __restrict__ b1,  const float* __restrict__ b2,
                                int n) {
    int idx = blockIdx.x * blockDim.x + threadIdx.x;   // float4 index over n*32
    if (idx >= n * 32) return;
    int v  = idx >> 5;
    int c4 = idx & 31;
    float s1 = g_dinv1[v]; s1 *= s1;
    float s2 = g_dinv2[v]; s2 *= s2;
    float4 a  = ((const float4*)xw1)[idx];
    float4 b  = ((const float4*)xw2)[idx];
    float4 v1 = ((const float4*)b1)[c4];
    float4 v2 = ((const float4*)b2)[c4];
    float4 o;
    o.x = a.x * s1 + b.x * s2 + v1.x + v2.x;
    o.y = a.y * s1 + b.y * s2 + v1.y + v2.y;
    o.z = a.z * s1 + b.z * s2 + v1.z + v2.z;
    o.w = a.w * s1 + b.w * s2 + v1.w + v2.w;
    ((float4*)out)[idx] = o;
}

// ---------------- edge scatter: out[dst] += xw[src] * norm  (1 warp / edge) ----------
__global__ void __launch_bounds__(256)
scatter_kernel(float* __restrict__ out, const float* __restrict__ xw,
               const int* __restrict__ src, const int* __restrict__ dst,
               const float* __restrict__ norm, int E) {
    int warp = (blockIdx.x * blockDim.x + threadIdx.x) >> 5;
    int lane = threadIdx.x & 31;
    if (warp >= E) return;
    int   s = src[warp];
    int   d = dst[warp];
    float w = norm[warp];
    float4 v = ((const float4*)(xw + (size_t)s * 128))[lane];
    float* o = out + (size_t)d * 128 + lane * 4;
    atomicAdd(o + 0, v.x * w);
    atomicAdd(o + 1, v.y * w);
    atomicAdd(o + 2, v.z * w);
    atomicAdd(o + 3, v.w * w);
}

// ---------------- host ----------------
extern "C" void kernel_launch(void* const* d_in, const int* in_sizes, int n_in,
                              void* d_out, int out_size) {
    const float* x  = (const float*)d_in[0];
    const void*  ei = d_in[1];
    const void*  ci = d_in[2];
    const float* Wc = (const float*)d_in[3];
    const float* bc = (const float*)d_in[4];
    const float* Wt = (const float*)d_in[5];
    const float* bt = (const float*)d_in[6];

    const int n  = in_sizes[0] / DIM;   // 100000
    const int E  = in_sizes[1] / 2;     // 600000
    const int EC = in_sizes[2] / 2;     // 200000

    float *xw1, *xw2, *xa, *xb, *dinv1, *dinv2, *norm1, *norm2;
    int *src1, *dst1, *src2, *dst2;
    cudaGetSymbolAddress((void**)&xw1,  g_xw1);
    cudaGetSymbolAddress((void**)&xw2,  g_xw2);
    cudaGetSymbolAddress((void**)&xa,   g_xa);
    cudaGetSymbolAddress((void**)&xb,   g_xb);
    cudaGetSymbolAddress((void**)&dinv1,g_dinv1);
    cudaGetSymbolAddress((void**)&dinv2,g_dinv2);
    cudaGetSymbolAddress((void**)&norm1,g_norm1);
    cudaGetSymbolAddress((void**)&norm2,g_norm2);
    cudaGetSymbolAddress((void**)&src1, g_src1);
    cudaGetSymbolAddress((void**)&dst1, g_dst1);
    cudaGetSymbolAddress((void**)&src2, g_src2);
    cudaGetSymbolAddress((void**)&dst2, g_dst2);

    // --- structure precompute (once; reused by all 4 layers) ---
    int chk = E < 65536 ? E : 65536;
    detect_kernel<<<1, 256>>>((const unsigned int*)ei, chk);
    decode_kernel<<<(E  + 255) / 256, 256>>>(ei, src1, dst1, E);
    decode_kernel<<<(EC + 255) / 256, 256>>>(ci, src2, dst2, EC);
    init_deg_kernel<<<(n + 255) / 256, 256>>>(n);
    count_deg_kernel<<<(E  + 255) / 256, 256>>>(dst1, dinv1, E);
    count_deg_kernel<<<(EC + 255) / 256, 256>>>(dst2, dinv2, EC);
    finish_dinv_kernel<<<(n + 255) / 256, 256>>>(n);
    compute_norm_kernel<<<(E  + 255) / 256, 256>>>(src1, dst1, dinv1, norm1, E);
    compute_norm_kernel<<<(EC + 255) / 256, 256>>>(src2, dst2, dinv2, norm2, EC);

    // --- 4 layers ---
    const float* cur = x;
    for (int i = 0; i < NDEPTH; i++) {
        float* nxt = (i == NDEPTH - 1) ? (float*)d_out : ((i & 1) ? xb : xa);

        dim3 ggrid((n + 127) / 128, 2);
        if (i == 0)
            gemm_dual_kernel<0><<<ggrid, 256>>>(cur, Wc + i * DIM * DIM, Wt + i * DIM * DIM, xw1, xw2, n);
        else
            gemm_dual_kernel<1><<<ggrid, 256>>>(cur, Wc + i * DIM * DIM, Wt + i * DIM * DIM, xw1, xw2, n);

        init_out_kernel<<<(n * 32 + 255) / 256, 256>>>(nxt, xw1, xw2, bc + i * DIM, bt + i * DIM, n);

        scatter_kernel<<<(E  + 7) / 8, 256>>>(nxt, xw1, src1, dst1, norm1, E);
        scatter_kernel<<<(EC + 7) / 8, 256>>>(nxt, xw2, src2, dst2, norm2, EC);

        cur = nxt;
    }
}

// round 5
// speedup vs baseline: 2.1329x; 2.1329x over previous
#include <cuda_runtime.h>
#include <cuda_bf16.h>
#include <cstdint>

#define N_NODES 100000
#define DIM     128
#define NE      600000
#define NEC     200000
#define NDEPTH  4

#define PAD   136                       // bf16 elems per smem row (272B: conflict-free ldmatrix)
#define WSTR  (128 * PAD * 2)           // bytes per W image in smem (34816)
#define ASTR  (64 * PAD * 2)            // bytes per A image in smem  (17408)
#define SM_TOTAL (4 * WSTR + 2 * ASTR)  // 174080 bytes

// ---------------- scratch (static device globals; no allocation) ----------------
__device__ float g_xw1[N_NODES * DIM];
__device__ float g_xw2[N_NODES * DIM];
__device__ float g_xa [N_NODES * DIM];
__device__ float g_xb [N_NODES * DIM];
__device__ float g_dinv1[N_NODES];
__device__ float g_dinv2[N_NODES];
__device__ float g_norm1[NE];
__device__ float g_norm2[NEC];
__device__ int   g_src1[NE],  g_dst1[NE];
__device__ int   g_src2[NEC], g_dst2[NEC];
__device__ int   g_is64;
// bf16 weight images, transposed [n][k]: [layer][conv_hi, conv_lo, ctrl_hi, ctrl_lo][128*128]
__device__ __nv_bfloat16 g_wimg[NDEPTH * 4 * DIM * DIM];

// ---------------- PTX helpers (base sm_103 features only) ----------------
__device__ __forceinline__ uint32_t smem_u32(const void* p) {
    uint32_t a;
    asm("{ .reg .u64 t; cvta.to.shared.u64 t, %1; cvt.u32.u64 %0, t; }" : "=r"(a) : "l"(p));
    return a;
}

__device__ __forceinline__ void ldm4(uint32_t* r, uint32_t addr) {
    asm volatile("ldmatrix.sync.aligned.m8n8.x4.shared.b16 {%0,%1,%2,%3}, [%4];"
                 : "=r"(r[0]), "=r"(r[1]), "=r"(r[2]), "=r"(r[3]) : "r"(addr));
}

__device__ __forceinline__ void mma_bf16(float* d, const uint32_t* a, uint32_t b0, uint32_t b1) {
    asm volatile("mma.sync.aligned.m16n8k16.row.col.f32.bf16.bf16.f32 "
                 "{%0,%1,%2,%3}, {%4,%5,%6,%7}, {%8,%9}, {%0,%1,%2,%3};"
                 : "+f"(d[0]), "+f"(d[1]), "+f"(d[2]), "+f"(d[3])
                 : "r"(a[0]), "r"(a[1]), "r"(a[2]), "r"(a[3]), "r"(b0), "r"(b1));
}

// ---------------- dtype autodetect: int64 edges have all-zero high words ----------------
__global__ void detect_kernel(const unsigned int* __restrict__ ebuf, int cnt) {
    __shared__ unsigned int acc;
    if (threadIdx.x == 0) acc = 0u;
    __syncthreads();
    unsigned int v = 0u;
    for (int i = threadIdx.x; i < cnt; i += blockDim.x) v |= ebuf[2 * i + 1];
    atomicOr(&acc, v);
    __syncthreads();
    if (threadIdx.x == 0) g_is64 = (acc == 0u) ? 1 : 0;
}

__global__ void decode_kernel(const void* __restrict__ ebuf,
                              int* __restrict__ src, int* __restrict__ dst, int E) {
    int i = blockIdx.x * blockDim.x + threadIdx.x;
    if (i >= E) return;
    if (g_is64) {
        const long long* p = (const long long*)ebuf;
        src[i] = (int)p[i];
        dst[i] = (int)p[E + i];
    } else {
        const int* p = (const int*)ebuf;
        src[i] = p[i];
        dst[i] = p[E + i];
    }
}

// ---------------- degree / norm precompute (once; reused all layers) ----------------
__global__ void init_deg_kernel(int n) {
    int i = blockIdx.x * blockDim.x + threadIdx.x;
    if (i < n) { g_dinv1[i] = 1.0f; g_dinv2[i] = 1.0f; }  // self-loop counts as 1
}
__global__ void count_deg_kernel(const int* __restrict__ dst, float* __restrict__ deg, int E) {
    int i = blockIdx.x * blockDim.x + threadIdx.x;
    if (i < E) atomicAdd(&deg[dst[i]], 1.0f);
}
__global__ void finish_dinv_kernel(int n) {
    int i = blockIdx.x * blockDim.x + threadIdx.x;
    if (i < n) { g_dinv1[i] = rsqrtf(g_dinv1[i]); g_dinv2[i] = rsqrtf(g_dinv2[i]); }
}
__global__ void compute_norm_kernel(const int* __restrict__ src, const int* __restrict__ dst,
                                    const float* __restrict__ dinv, float* __restrict__ norm, int E) {
    int i = blockIdx.x * blockDim.x + threadIdx.x;
    if (i < E) norm[i] = dinv[src[i]] * dinv[dst[i]];
}

// ---------------- W prep: fp32 W[k][n] -> bf16 hi/lo transposed Wt[n][k] ----------------
__global__ void prep_w_kernel(const float* __restrict__ Wc, const float* __restrict__ Wt) {
    int m = blockIdx.y;                 // 0..7 : layer*2 + gemm
    int l = m >> 1, g = m & 1;
    const float* W = (g ? Wt : Wc) + l * DIM * DIM;
    int idx = blockIdx.x * 256 + threadIdx.x;     // 0..16383
    int k = idx >> 7, nn = idx & 127;
    float v = W[k * 128 + nn];
    __nv_bfloat16 h  = __float2bfloat16(v);
    __nv_bfloat16 lo = __float2bfloat16(v - __bfloat162float(h));
    __nv_bfloat16* base = g_wimg + (size_t)l * 4 * 16384 + (size_t)(g * 2) * 16384;
    base[nn * 128 + k]         = h;     // hi image
    base[16384 + nn * 128 + k] = lo;    // lo image
}

// ---------------- persistent fused GEMM (mma.sync bf16 3x split) + epilogue -------------
// Block: 256 thr = 8 warps (warp_m = wid&1 -> 32 rows, warp_n = wid>>1 -> 32 cols).
// Each block loads all 4 W images once, loops over 64-row A tiles.
// Computes D1 = A@W1, D2 = A@W2 for its tile; epilogue writes xw1, xw2 and
// nxt = D1*dinv1^2 + D2*dinv2^2 + b1 + b2 (fused self-loop + bias init).
template <int RELU>
__global__ void __launch_bounds__(256, 1)
gemm_mma_kernel(const float* __restrict__ A, const __nv_bfloat16* __restrict__ wimg,
                float* __restrict__ xw1, float* __restrict__ xw2, float* __restrict__ nxt,
                const float* __restrict__ dinv1, const float* __restrict__ dinv2,
                const float* __restrict__ b1, const float* __restrict__ b2,
                int n, int ntiles) {
    extern __shared__ char sm[];
    const uint32_t sbase = smem_u32(sm);
    const uint32_t Wb   = sbase;                 // 4 W images
    const uint32_t Ahib = sbase + 4 * WSTR;      // A hi
    const uint32_t Alob = Ahib + ASTR;           // A lo

    const int tid  = threadIdx.x;
    const int wid  = tid >> 5;
    const int lane = tid & 31;
    const int warp_m = wid & 1;
    const int warp_n = wid >> 1;
    const int tr  = lane & 7;
    const int sel = lane >> 3;

    // ---- load all W images into smem (once) ----
    for (int i = tid; i < 8192; i += 256) {      // uint4 chunks
        int arr = i >> 11;
        int rem = i & 2047;
        int row = rem >> 4;
        int ch  = rem & 15;
        uint4 v = *(const uint4*)(wimg + (size_t)arr * 16384 + row * 128 + ch * 8);
        *(uint4*)(sm + arr * WSTR + row * PAD * 2 + ch * 16) = v;
    }

    // per-thread fragment base offsets (bytes)
    const uint32_t a_off = (uint32_t)((warp_m * 32 + (sel & 1) * 8 + tr) * PAD + (sel >> 1) * 8) * 2;
    const uint32_t b_off = (uint32_t)((warp_n * 32 + (sel >> 1) * 8 + tr) * PAD + (sel & 1) * 8) * 2;

    // bias sums for this thread's columns
    const int tq = lane & 3;
    float2 bs[4];
#pragma unroll
    for (int j = 0; j < 4; j++) {
        int c = warp_n * 32 + j * 8 + tq * 2;
        bs[j].x = b1[c]     + b2[c];
        bs[j].y = b1[c + 1] + b2[c + 1];
    }

    for (int tile = blockIdx.x; tile < ntiles; tile += gridDim.x) {
        const int row0 = tile * 64;
        __syncthreads();   // previous iteration's reads of A smem complete

        // ---- A tile load + ReLU + bf16 hi/lo split ----
        const float4* Ap = (const float4*)A;
        for (int i = tid; i < 2048; i += 256) {  // 64 rows x 32 float4
            int row = i >> 5;
            int q   = i & 31;
            float4 v = make_float4(0.f, 0.f, 0.f, 0.f);
            if (row0 + row < n) v = Ap[(size_t)(row0 + row) * 32 + q];
            if (RELU) {
                v.x = fmaxf(v.x, 0.f); v.y = fmaxf(v.y, 0.f);
                v.z = fmaxf(v.z, 0.f); v.w = fmaxf(v.w, 0.f);
            }
            __nv_bfloat16 h0 = __float2bfloat16(v.x), h1 = __float2bfloat16(v.y);
            __nv_bfloat16 h2 = __float2bfloat16(v.z), h3 = __float2bfloat16(v.w);
            __nv_bfloat16 l0 = __float2bfloat16(v.x - __bfloat162float(h0));
            __nv_bfloat16 l1 = __float2bfloat16(v.y - __bfloat162float(h1));
            __nv_bfloat16 l2 = __float2bfloat16(v.z - __bfloat162float(h2));
            __nv_bfloat16 l3 = __float2bfloat16(v.w - __bfloat162float(h3));
            uint2 hw, lw;
            hw.x = (uint32_t)__bfloat16_as_ushort(h0) | ((uint32_t)__bfloat16_as_ushort(h1) << 16);
            hw.y = (uint32_t)__bfloat16_as_ushort(h2) | ((uint32_t)__bfloat16_as_ushort(h3) << 16);
            lw.x = (uint32_t)__bfloat16_as_ushort(l0) | ((uint32_t)__bfloat16_as_ushort(l1) << 16);
            lw.y = (uint32_t)__bfloat16_as_ushort(l2) | ((uint32_t)__bfloat16_as_ushort(l3) << 16);
            uint32_t off = (uint32_t)(row * PAD + q * 4) * 2;
            *(uint2*)(sm + (4 * WSTR) + off)        = hw;
            *(uint2*)(sm + (4 * WSTR) + ASTR + off) = lw;
        }
        __syncthreads();

        // ---- compute: D1, D2 accumulate over K=128 ----
        float acc1[8][4], acc2[8][4];
#pragma unroll
        for (int t = 0; t < 8; t++)
#pragma unroll
            for (int e = 0; e < 4; e++) { acc1[t][e] = 0.f; acc2[t][e] = 0.f; }

#pragma unroll
        for (int ks = 0; ks < 8; ks++) {
            const uint32_t kb = ks * 32;    // k0*2 bytes
            uint32_t ah[2][4], al[2][4];
            ldm4(ah[0], Ahib + a_off + kb);
            ldm4(ah[1], Ahib + a_off + 16 * PAD * 2 + kb);
            ldm4(al[0], Alob + a_off + kb);
            ldm4(al[1], Alob + a_off + 16 * PAD * 2 + kb);
#pragma unroll
            for (int g = 0; g < 2; g++) {
                float (*acc)[4] = g ? acc2 : acc1;
#pragma unroll
                for (int jp = 0; jp < 2; jp++) {
                    uint32_t wh[4], wl[4];
                    uint32_t wb = Wb + (uint32_t)(g * 2) * WSTR + b_off + jp * 16 * PAD * 2 + kb;
                    ldm4(wh, wb);
                    ldm4(wl, wb + WSTR);
#pragma unroll
                    for (int i = 0; i < 2; i++)
#pragma unroll
                        for (int jj = 0; jj < 2; jj++) {
                            float* d = acc[i * 4 + jp * 2 + jj];
                            mma_bf16(d, ah[i], wh[jj * 2], wh[jj * 2 + 1]);
                            mma_bf16(d, ah[i], wl[jj * 2], wl[jj * 2 + 1]);
                            mma_bf16(d, al[i], wh[jj * 2], wh[jj * 2 + 1]);
                        }
                }
            }
        }

        // ---- fused epilogue ----
#pragma unroll
        for (int i = 0; i < 2; i++) {
            int ra = row0 + warp_m * 32 + i * 16 + (lane >> 2);
            int rb = ra + 8;
            float s1a = 0.f, s2a = 0.f, s1b = 0.f, s2b = 0.f;
            if (ra < n) { s1a = dinv1[ra]; s1a *= s1a; s2a = dinv2[ra]; s2a *= s2a; }
            if (rb < n) { s1b = dinv1[rb]; s1b *= s1b; s2b = dinv2[rb]; s2b *= s2b; }
#pragma unroll
            for (int j = 0; j < 4; j++) {
                int t = i * 4 + j;
                int c = warp_n * 32 + j * 8 + tq * 2;
                if (ra < n) {
                    size_t o = (size_t)ra * 128 + c;
                    *(float2*)&xw1[o] = make_float2(acc1[t][0], acc1[t][1]);
                    *(float2*)&xw2[o] = make_float2(acc2[t][0], acc2[t][1]);
                    *(float2*)&nxt[o] = make_float2(
                        acc1[t][0] * s1a + acc2[t][0] * s2a + bs[j].x,
                        acc1[t][1] * s1a + acc2[t][1] * s2a + bs[j].y);
                }
                if (rb < n) {
                    size_t o = (size_t)rb * 128 + c;
                    *(float2*)&xw1[o] = make_float2(acc1[t][2], acc1[t][3]);
                    *(float2*)&xw2[o] = make_float2(acc2[t][2], acc2[t][3]);
                    *(float2*)&nxt[o] = make_float2(
                        acc1[t][2] * s1b + acc2[t][2] * s2b + bs[j].x,
                        acc1[t][3] * s1b + acc2[t][3] * s2b + bs[j].y);
                }
            }
        }
    }
}

// ---------------- edge scatter: out[dst] += xw[src] * norm (warp/edge, red.v4) ----------
__global__ void __launch_bounds__(256)
scatter_kernel(float* __restrict__ out, const float* __restrict__ xw,
               const int* __restrict__ src, const int* __restrict__ dst,
               const float* __restrict__ norm, int E) {
    int warp = (blockIdx.x * blockDim.x + threadIdx.x) >> 5;
    int lane = threadIdx.x & 31;
    if (warp >= E) return;
    int   s = src[warp];
    int   d = dst[warp];
    float w = norm[warp];
    float4 v = ((const float4*)(xw + (size_t)s * 128))[lane];
    float* o = out + (size_t)d * 128 + lane * 4;
    asm volatile("red.global.add.v4.f32 [%0], {%1, %2, %3, %4};"
                 :: "l"(o), "f"(v.x * w), "f"(v.y * w), "f"(v.z * w), "f"(v.w * w)
                 : "memory");
}

// ---------------- host ----------------
extern "C" void kernel_launch(void* const* d_in, const int* in_sizes, int n_in,
                              void* d_out, int out_size) {
    const float* x  = (const float*)d_in[0];
    const void*  ei = d_in[1];
    const void*  ci = d_in[2];
    const float* Wc = (const float*)d_in[3];
    const float* bc = (const float*)d_in[4];
    const float* Wt = (const float*)d_in[5];
    const float* bt = (const float*)d_in[6];

    const int n  = in_sizes[0] / DIM;   // 100000
    const int E  = in_sizes[1] / 2;     // 600000
    const int EC = in_sizes[2] / 2;     // 200000

    float *xw1, *xw2, *xa, *xb, *dinv1, *dinv2, *norm1, *norm2;
    int *src1, *dst1, *src2, *dst2;
    __nv_bfloat16* wimg;
    cudaGetSymbolAddress((void**)&xw1,  g_xw1);
    cudaGetSymbolAddress((void**)&xw2,  g_xw2);
    cudaGetSymbolAddress((void**)&xa,   g_xa);
    cudaGetSymbolAddress((void**)&xb,   g_xb);
    cudaGetSymbolAddress((void**)&dinv1,g_dinv1);
    cudaGetSymbolAddress((void**)&dinv2,g_dinv2);
    cudaGetSymbolAddress((void**)&norm1,g_norm1);
    cudaGetSymbolAddress((void**)&norm2,g_norm2);
    cudaGetSymbolAddress((void**)&src1, g_src1);
    cudaGetSymbolAddress((void**)&dst1, g_dst1);
    cudaGetSymbolAddress((void**)&src2, g_src2);
    cudaGetSymbolAddress((void**)&dst2, g_dst2);
    cudaGetSymbolAddress((void**)&wimg, g_wimg);

    cudaFuncSetAttribute(gemm_mma_kernel<0>, cudaFuncAttributeMaxDynamicSharedMemorySize, SM_TOTAL);
    cudaFuncSetAttribute(gemm_mma_kernel<1>, cudaFuncAttributeMaxDynamicSharedMemorySize, SM_TOTAL);

    // --- precompute (once; reused by all layers) ---
    int chk = E < 65536 ? E : 65536;
    detect_kernel<<<1, 256>>>((const unsigned int*)ei, chk);
    decode_kernel<<<(E  + 255) / 256, 256>>>(ei, src1, dst1, E);
    decode_kernel<<<(EC + 255) / 256, 256>>>(ci, src2, dst2, EC);
    init_deg_kernel<<<(n + 255) / 256, 256>>>(n);
    count_deg_kernel<<<(E  + 255) / 256, 256>>>(dst1, dinv1, E);
    count_deg_kernel<<<(EC + 255) / 256, 256>>>(dst2, dinv2, EC);
    finish_dinv_kernel<<<(n + 255) / 256, 256>>>(n);
    compute_norm_kernel<<<(E  + 255) / 256, 256>>>(src1, dst1, dinv1, norm1, E);
    compute_norm_kernel<<<(EC + 255) / 256, 256>>>(src2, dst2, dinv2, norm2, EC);
    {
        dim3 pw(64, 8);
        prep_w_kernel<<<pw, 256>>>(Wc, Wt);
    }

    // --- 4 layers ---
    const int ntiles = (n + 63) / 64;
    const int gblocks = 148;
    const float* cur = x;
    for (int i = 0; i < NDEPTH; i++) {
        float* nxt = (i == NDEPTH - 1) ? (float*)d_out : ((i & 1) ? xb : xa);
        const __nv_bfloat16* wl = wimg + (size_t)i * 4 * 16384;
        if (i == 0)
            gemm_mma_kernel<0><<<gblocks, 256, SM_TOTAL>>>(cur, wl, xw1, xw2, nxt,
                dinv1, dinv2, bc + i * DIM, bt + i * DIM, n, ntiles);
        else
            gemm_mma_kernel<1><<<gblocks, 256, SM_TOTAL>>>(cur, wl, xw1, xw2, nxt,
                dinv1, dinv2, bc + i * DIM, bt + i * DIM, n, ntiles);

        scatter_kernel<<<(E  + 7) / 8, 256>>>(nxt, xw1, src1, dst1, norm1, E);
        scatter_kernel<<<(EC + 7) / 8, 256>>>(nxt, xw2, src2, dst2, norm2, EC);

        cur = nxt;
    }
}

// round 6
// speedup vs baseline: 2.5347x; 1.1884x over previous
#include <cuda_runtime.h>
#include <cuda_bf16.h>
#include <cstdint>

#define N_NODES 100000
#define DIM     128
#define NE      600000
#define NEC     200000
#define NETOT   (NE + NEC)
#define NDEPTH  4

#define PAD   136                       // bf16 elems per smem row (272B: conflict-free ldmatrix)
#define WSTR  (128 * PAD * 2)           // bytes per W image in smem (34816)
#define ASTR  (64 * PAD * 2)            // bytes per A image in smem  (17408)
#define SM_TOTAL (4 * WSTR + 2 * ASTR)  // 174080 bytes

// ---------------- scratch (static device globals; no allocation) ----------------
__device__ float g_xw1[N_NODES * DIM];
__device__ float g_xw2[N_NODES * DIM];
__device__ float g_xa [N_NODES * DIM];
__device__ float g_xb [N_NODES * DIM];
__device__ float g_dinv1[N_NODES];      // holds degree during count, then rsqrt(deg)
__device__ float g_dinv2[N_NODES];
__device__ int   g_cnt[N_NODES];        // combined in-degree (CSR row sizes)
__device__ int   g_rowptr[N_NODES + 1];
__device__ int   g_wcur[N_NODES];       // fill cursors
__device__ int   g_blocksum[512];
__device__ int2  g_entry[NETOT];        // {src | flag<<31, norm bits}
__device__ int   g_is64;
// bf16 weight images, transposed [n][k]: [layer][conv_hi, conv_lo, ctrl_hi, ctrl_lo]
__device__ __nv_bfloat16 g_wimg[NDEPTH * 4 * DIM * DIM];

// ---------------- PTX helpers (base sm_103 features only) ----------------
__device__ __forceinline__ uint32_t smem_u32(const void* p) {
    uint32_t a;
    asm("{ .reg .u64 t; cvta.to.shared.u64 t, %1; cvt.u32.u64 %0, t; }" : "=r"(a) : "l"(p));
    return a;
}
__device__ __forceinline__ void ldm4(uint32_t* r, uint32_t addr) {
    asm volatile("ldmatrix.sync.aligned.m8n8.x4.shared.b16 {%0,%1,%2,%3}, [%4];"
                 : "=r"(r[0]), "=r"(r[1]), "=r"(r[2]), "=r"(r[3]) : "r"(addr));
}
__device__ __forceinline__ void mma_bf16(float* d, const uint32_t* a, uint32_t b0, uint32_t b1) {
    asm volatile("mma.sync.aligned.m16n8k16.row.col.f32.bf16.bf16.f32 "
                 "{%0,%1,%2,%3}, {%4,%5,%6,%7}, {%8,%9}, {%0,%1,%2,%3};"
                 : "+f"(d[0]), "+f"(d[1]), "+f"(d[2]), "+f"(d[3])
                 : "r"(a[0]), "r"(a[1]), "r"(a[2]), "r"(a[3]), "r"(b0), "r"(b1));
}

// ---------------- raw edge parse helpers ----------------
__device__ __forceinline__ int edge_val(const void* buf, long long idx) {
    if (g_is64) return (int)((const long long*)buf)[idx];
    return ((const int*)buf)[idx];
}

// ---------------- dtype autodetect: int64 edges have all-zero high words ----------------
__global__ void detect_kernel(const unsigned int* __restrict__ ebuf, int cnt) {
    __shared__ unsigned int acc;
    if (threadIdx.x == 0) acc = 0u;
    __syncthreads();
    unsigned int v = 0u;
    for (int i = threadIdx.x; i < cnt; i += blockDim.x) v |= ebuf[2 * i + 1];
    atomicOr(&acc, v);
    __syncthreads();
    if (threadIdx.x == 0) g_is64 = (acc == 0u) ? 1 : 0;
}

// ---------------- degree init + count (self-loop counts as 1) ----------------
__global__ void init_deg_kernel(int n) {
    int i = blockIdx.x * blockDim.x + threadIdx.x;
    if (i < n) { g_dinv1[i] = 1.0f; g_dinv2[i] = 1.0f; }
}
__global__ void count_deg_kernel(const void* __restrict__ ebuf, const void* __restrict__ cbuf,
                                 int E, int EC) {
    int i = blockIdx.x * blockDim.x + threadIdx.x;
    if (i >= E + EC) return;
    if (i < E) {
        int d = edge_val(ebuf, (long long)E + i);
        atomicAdd(&g_dinv1[d], 1.0f);
    } else {
        int j = i - E;
        int d = edge_val(cbuf, (long long)EC + j);
        atomicAdd(&g_dinv2[d], 1.0f);
    }
}

// ---------------- dinv = rsqrt(deg); cnt = combined indeg; per-block sums ----------------
__global__ void dinv_cnt_kernel(int n) {
    __shared__ int sdata[256];
    int i = blockIdx.x * blockDim.x + threadIdx.x;
    int c = 0;
    if (i < n) {
        float d1 = g_dinv1[i], d2 = g_dinv2[i];
        c = (int)(d1 + d2) - 2;             // exclude the two self-loops
        g_cnt[i] = c;
        g_dinv1[i] = rsqrtf(d1);
        g_dinv2[i] = rsqrtf(d2);
    }
    sdata[threadIdx.x] = c;
    __syncthreads();
    for (int off = 128; off > 0; off >>= 1) {
        if (threadIdx.x < off) sdata[threadIdx.x] += sdata[threadIdx.x + off];
        __syncthreads();
    }
    if (threadIdx.x == 0) g_blocksum[blockIdx.x] = sdata[0];
}

// ---------------- scan block sums (one block; nb <= 512) ----------------
__global__ void scan_blocks_kernel(int nb, int n) {
    __shared__ int s[512];
    int t = threadIdx.x;
    s[t] = (t < nb) ? g_blocksum[t] : 0;
    __syncthreads();
    if (t == 0) {
        int run = 0;
        for (int b = 0; b < nb; b++) { int v = s[b]; s[b] = run; run += v; }
        g_rowptr[n] = run;
    }
    __syncthreads();
    if (t < nb) g_blocksum[t] = s[t];
}

// ---------------- rowptr: block exclusive scan + block offset ----------------
__global__ void rowptr_kernel(int n) {
    __shared__ int s[256];
    int i = blockIdx.x * blockDim.x + threadIdx.x;
    int t = threadIdx.x;
    int v = (i < n) ? g_cnt[i] : 0;
    s[t] = v;
    __syncthreads();
#pragma unroll
    for (int off = 1; off < 256; off <<= 1) {
        int add = (t >= off) ? s[t - off] : 0;
        __syncthreads();
        s[t] += add;
        __syncthreads();
    }
    if (i < n) {
        int excl = s[t] - v + g_blocksum[blockIdx.x];
        g_rowptr[i] = excl;
        g_wcur[i]   = excl;
    }
}

// ---------------- fill CSR entries: {src | flag<<31, norm} ----------------
__global__ void fill_kernel(const void* __restrict__ ebuf, const void* __restrict__ cbuf,
                            int E, int EC) {
    int i = blockIdx.x * blockDim.x + threadIdx.x;
    if (i >= E + EC) return;
    int s, d, flag;
    float nm;
    if (i < E) {
        s = edge_val(ebuf, i);
        d = edge_val(ebuf, (long long)E + i);
        nm = g_dinv1[s] * g_dinv1[d];
        flag = 0;
    } else {
        int j = i - E;
        s = edge_val(cbuf, j);
        d = edge_val(cbuf, (long long)EC + j);
        nm = g_dinv2[s] * g_dinv2[d];
        flag = 1;
    }
    int pos = atomicAdd(&g_wcur[d], 1);
    g_entry[pos] = make_int2(s | (flag << 31), __float_as_int(nm));
}

// ---------------- W prep: fp32 W[k][n] -> bf16 hi/lo transposed Wt[n][k] ----------------
__global__ void prep_w_kernel(const float* __restrict__ Wc, const float* __restrict__ Wt) {
    int m = blockIdx.y;                 // 0..7 : layer*2 + gemm
    int l = m >> 1, g = m & 1;
    const float* W = (g ? Wt : Wc) + l * DIM * DIM;
    int idx = blockIdx.x * 256 + threadIdx.x;     // 0..16383
    int k = idx >> 7, nn = idx & 127;
    float v = W[k * 128 + nn];
    __nv_bfloat16 h  = __float2bfloat16(v);
    __nv_bfloat16 lo = __float2bfloat16(v - __bfloat162float(h));
    __nv_bfloat16* base = g_wimg + (size_t)l * 4 * 16384 + (size_t)(g * 2) * 16384;
    base[nn * 128 + k]         = h;     // hi image
    base[16384 + nn * 128 + k] = lo;    // lo image
}

// ---------------- persistent fused GEMM (mma.sync bf16 3x split) + epilogue -------------
template <int RELU>
__global__ void __launch_bounds__(256, 1)
gemm_mma_kernel(const float* __restrict__ A, const __nv_bfloat16* __restrict__ wimg,
                float* __restrict__ xw1, float* __restrict__ xw2, float* __restrict__ nxt,
                const float* __restrict__ dinv1, const float* __restrict__ dinv2,
                const float* __restrict__ b1, const float* __restrict__ b2,
                int n, int ntiles) {
    extern __shared__ char sm[];
    const uint32_t sbase = smem_u32(sm);
    const uint32_t Wb   = sbase;
    const uint32_t Ahib = sbase + 4 * WSTR;
    const uint32_t Alob = Ahib + ASTR;

    const int tid  = threadIdx.x;
    const int wid  = tid >> 5;
    const int lane = tid & 31;
    const int warp_m = wid & 1;
    const int warp_n = wid >> 1;
    const int tr  = lane & 7;
    const int sel = lane >> 3;

    for (int i = tid; i < 8192; i += 256) {      // W images -> smem (uint4)
        int arr = i >> 11;
        int rem = i & 2047;
        int row = rem >> 4;
        int ch  = rem & 15;
        uint4 v = *(const uint4*)(wimg + (size_t)arr * 16384 + row * 128 + ch * 8);
        *(uint4*)(sm + arr * WSTR + row * PAD * 2 + ch * 16) = v;
    }

    const uint32_t a_off = (uint32_t)((warp_m * 32 + (sel & 1) * 8 + tr) * PAD + (sel >> 1) * 8) * 2;
    const uint32_t b_off = (uint32_t)((warp_n * 32 + (sel >> 1) * 8 + tr) * PAD + (sel & 1) * 8) * 2;

    const int tq = lane & 3;
    float2 bs[4];
#pragma unroll
    for (int j = 0; j < 4; j++) {
        int c = warp_n * 32 + j * 8 + tq * 2;
        bs[j].x = b1[c]     + b2[c];
        bs[j].y = b1[c + 1] + b2[c + 1];
    }

    for (int tile = blockIdx.x; tile < ntiles; tile += gridDim.x) {
        const int row0 = tile * 64;
        __syncthreads();

        const float4* Ap = (const float4*)A;
        for (int i = tid; i < 2048; i += 256) {  // 64 rows x 32 float4
            int row = i >> 5;
            int q   = i & 31;
            float4 v = make_float4(0.f, 0.f, 0.f, 0.f);
            if (row0 + row < n) v = Ap[(size_t)(row0 + row) * 32 + q];
            if (RELU) {
                v.x = fmaxf(v.x, 0.f); v.y = fmaxf(v.y, 0.f);
                v.z = fmaxf(v.z, 0.f); v.w = fmaxf(v.w, 0.f);
            }
            __nv_bfloat16 h0 = __float2bfloat16(v.x), h1 = __float2bfloat16(v.y);
            __nv_bfloat16 h2 = __float2bfloat16(v.z), h3 = __float2bfloat16(v.w);
            __nv_bfloat16 l0 = __float2bfloat16(v.x - __bfloat162float(h0));
            __nv_bfloat16 l1 = __float2bfloat16(v.y - __bfloat162float(h1));
            __nv_bfloat16 l2 = __float2bfloat16(v.z - __bfloat162float(h2));
            __nv_bfloat16 l3 = __float2bfloat16(v.w - __bfloat162float(h3));
            uint2 hw, lw;
            hw.x = (uint32_t)__bfloat16_as_ushort(h0) | ((uint32_t)__bfloat16_as_ushort(h1) << 16);
            hw.y = (uint32_t)__bfloat16_as_ushort(h2) | ((uint32_t)__bfloat16_as_ushort(h3) << 16);
            lw.x = (uint32_t)__bfloat16_as_ushort(l0) | ((uint32_t)__bfloat16_as_ushort(l1) << 16);
            lw.y = (uint32_t)__bfloat16_as_ushort(l2) | ((uint32_t)__bfloat16_as_ushort(l3) << 16);
            uint32_t off = (uint32_t)(row * PAD + q * 4) * 2;
            *(uint2*)(sm + (4 * WSTR) + off)        = hw;
            *(uint2*)(sm + (4 * WSTR) + ASTR + off) = lw;
        }
        __syncthreads();

        float acc1[8][4], acc2[8][4];
#pragma unroll
        for (int t = 0; t < 8; t++)
#pragma unroll
            for (int e = 0; e < 4; e++) { acc1[t][e] = 0.f; acc2[t][e] = 0.f; }

#pragma unroll
        for (int ks = 0; ks < 8; ks++) {
            const uint32_t kb = ks * 32;
            uint32_t ah[2][4], al[2][4];
            ldm4(ah[0], Ahib + a_off + kb);
            ldm4(ah[1], Ahib + a_off + 16 * PAD * 2 + kb);
            ldm4(al[0], Alob + a_off + kb);
            ldm4(al[1], Alob + a_off + 16 * PAD * 2 + kb);
#pragma unroll
            for (int g = 0; g < 2; g++) {
                float (*acc)[4] = g ? acc2 : acc1;
#pragma unroll
                for (int jp = 0; jp < 2; jp++) {
                    uint32_t wh[4], wl[4];
                    uint32_t wb = Wb + (uint32_t)(g * 2) * WSTR + b_off + jp * 16 * PAD * 2 + kb;
                    ldm4(wh, wb);
                    ldm4(wl, wb + WSTR);
#pragma unroll
                    for (int i = 0; i < 2; i++)
#pragma unroll
                        for (int jj = 0; jj < 2; jj++) {
                            float* d = acc[i * 4 + jp * 2 + jj];
                            mma_bf16(d, ah[i], wh[jj * 2], wh[jj * 2 + 1]);
                            mma_bf16(d, ah[i], wl[jj * 2], wl[jj * 2 + 1]);
                            mma_bf16(d, al[i], wh[jj * 2], wh[jj * 2 + 1]);
                        }
                }
            }
        }

#pragma unroll
        for (int i = 0; i < 2; i++) {
            int ra = row0 + warp_m * 32 + i * 16 + (lane >> 2);
            int rb = ra + 8;
            float s1a = 0.f, s2a = 0.f, s1b = 0.f, s2b = 0.f;
            if (ra < n) { s1a = dinv1[ra]; s1a *= s1a; s2a = dinv2[ra]; s2a *= s2a; }
            if (rb < n) { s1b = dinv1[rb]; s1b *= s1b; s2b = dinv2[rb]; s2b *= s2b; }
#pragma unroll
            for (int j = 0; j < 4; j++) {
                int t = i * 4 + j;
                int c = warp_n * 32 + j * 8 + tq * 2;
                if (ra < n) {
                    size_t o = (size_t)ra * 128 + c;
                    *(float2*)&xw1[o] = make_float2(acc1[t][0], acc1[t][1]);
                    *(float2*)&xw2[o] = make_float2(acc2[t][0], acc2[t][1]);
                    *(float2*)&nxt[o] = make_float2(
                        acc1[t][0] * s1a + acc2[t][0] * s2a + bs[j].x,
                        acc1[t][1] * s1a + acc2[t][1] * s2a + bs[j].y);
                }
                if (rb < n) {
                    size_t o = (size_t)rb * 128 + c;
                    *(float2*)&xw1[o] = make_float2(acc1[t][2], acc1[t][3]);
                    *(float2*)&xw2[o] = make_float2(acc2[t][2], acc2[t][3]);
                    *(float2*)&nxt[o] = make_float2(
                        acc1[t][2] * s1b + acc2[t][2] * s2b + bs[j].x,
                        acc1[t][3] * s1b + acc2[t][3] * s2b + bs[j].y);
                }
            }
        }
    }
}

// ---------------- CSR scatter: warp/node, no atomics ----------------
// nxt[v] already holds self-loop + bias terms (GEMM epilogue); accumulate in-edges.
__global__ void __launch_bounds__(256)
scatter_csr_kernel(float* __restrict__ nxt,
                   const float* __restrict__ xw1, const float* __restrict__ xw2,
                   const int* __restrict__ rowptr, const int2* __restrict__ entry, int n) {
    int v    = (blockIdx.x * blockDim.x + threadIdx.x) >> 5;
    int lane = threadIdx.x & 31;
    if (v >= n) return;
    int e0 = rowptr[v];
    int e1 = rowptr[v + 1];
    float4 acc = ((const float4*)(nxt + (size_t)v * 128))[lane];
    int e = e0;
    // unrolled-by-2 for MLP
    for (; e + 1 < e1; e += 2) {
        int2 ea = __ldg(&entry[e]);
        int2 eb = __ldg(&entry[e + 1]);
        const float* ba = (ea.x < 0) ? xw2 : xw1;
        const float* bb = (eb.x < 0) ? xw2 : xw1;
        int   sa = ea.x & 0x7FFFFFFF, sb = eb.x & 0x7FFFFFFF;
        float wa = __int_as_float(ea.y), wb = __int_as_float(eb.y);
        float4 va = ((const float4*)(ba + (size_t)sa * 128))[lane];
        float4 vb = ((const float4*)(bb + (size_t)sb * 128))[lane];
        acc.x += va.x * wa; acc.y += va.y * wa; acc.z += va.z * wa; acc.w += va.w * wa;
        acc.x += vb.x * wb; acc.y += vb.y * wb; acc.z += vb.z * wb; acc.w += vb.w * wb;
    }
    if (e < e1) {
        int2 ea = __ldg(&entry[e]);
        const float* ba = (ea.x < 0) ? xw2 : xw1;
        int   sa = ea.x & 0x7FFFFFFF;
        float wa = __int_as_float(ea.y);
        float4 va = ((const float4*)(ba + (size_t)sa * 128))[lane];
        acc.x += va.x * wa; acc.y += va.y * wa; acc.z += va.z * wa; acc.w += va.w * wa;
    }
    ((float4*)(nxt + (size_t)v * 128))[lane] = acc;
}

// ---------------- host ----------------
extern "C" void kernel_launch(void* const* d_in, const int* in_sizes, int n_in,
                              void* d_out, int out_size) {
    const float* x  = (const float*)d_in[0];
    const void*  ei = d_in[1];
    const void*  ci = d_in[2];
    const float* Wc = (const float*)d_in[3];
    const float* bc = (const float*)d_in[4];
    const float* Wt = (const float*)d_in[5];
    const float* bt = (const float*)d_in[6];

    const int n  = in_sizes[0] / DIM;   // 100000
    const int E  = in_sizes[1] / 2;     // 600000
    const int EC = in_sizes[2] / 2;     // 200000

    float *xw1, *xw2, *xa, *xb, *dinv1, *dinv2;
    int *rowptr; int2 *entry;
    __nv_bfloat16* wimg;
    cudaGetSymbolAddress((void**)&xw1,   g_xw1);
    cudaGetSymbolAddress((void**)&xw2,   g_xw2);
    cudaGetSymbolAddress((void**)&xa,    g_xa);
    cudaGetSymbolAddress((void**)&xb,    g_xb);
    cudaGetSymbolAddress((void**)&dinv1, g_dinv1);
    cudaGetSymbolAddress((void**)&dinv2, g_dinv2);
    cudaGetSymbolAddress((void**)&rowptr,g_rowptr);
    cudaGetSymbolAddress((void**)&entry, g_entry);
    cudaGetSymbolAddress((void**)&wimg,  g_wimg);

    cudaFuncSetAttribute(gemm_mma_kernel<0>, cudaFuncAttributeMaxDynamicSharedMemorySize, SM_TOTAL);
    cudaFuncSetAttribute(gemm_mma_kernel<1>, cudaFuncAttributeMaxDynamicSharedMemorySize, SM_TOTAL);

    const int nb = (n + 255) / 256;     // 391 blocks

    // --- precompute: degrees, dinv, CSR (once; reused by all layers) ---
    int chk = E < 65536 ? E : 65536;
    detect_kernel<<<1, 256>>>((const unsigned int*)ei, chk);
    init_deg_kernel<<<nb, 256>>>(n);
    count_deg_kernel<<<(E + EC + 255) / 256, 256>>>(ei, ci, E, EC);
    dinv_cnt_kernel<<<nb, 256>>>(n);
    scan_blocks_kernel<<<1, 512>>>(nb, n);
    rowptr_kernel<<<nb, 256>>>(n);
    fill_kernel<<<(E + EC + 255) / 256, 256>>>(ei, ci, E, EC);
    {
        dim3 pw(64, 8);
        prep_w_kernel<<<pw, 256>>>(Wc, Wt);
    }

    // --- 4 layers ---
    const int ntiles = (n + 63) / 64;
    const int gblocks = 148;
    const float* cur = x;
    for (int i = 0; i < NDEPTH; i++) {
        float* nxt = (i == NDEPTH - 1) ? (float*)d_out : ((i & 1) ? xb : xa);
        const __nv_bfloat16* wl = wimg + (size_t)i * 4 * 16384;
        if (i == 0)
            gemm_mma_kernel<0><<<gblocks, 256, SM_TOTAL>>>(cur, wl, xw1, xw2, nxt,
                dinv1, dinv2, bc + i * DIM, bt + i * DIM, n, ntiles);
        else
            gemm_mma_kernel<1><<<gblocks, 256, SM_TOTAL>>>(cur, wl, xw1, xw2, nxt,
                dinv1, dinv2, bc + i * DIM, bt + i * DIM, n, ntiles);

        scatter_csr_kernel<<<(n * 32 + 255) / 256, 256>>>(nxt, xw1, xw2, rowptr, entry, n);

        cur = nxt;
    }
}

// round 7
// speedup vs baseline: 3.1196x; 1.2308x over previous
#include <cuda_runtime.h>
#include <cuda_bf16.h>
#include <cstdint>

#define N_NODES 100000
#define DIM     128
#define NE      600000
#define NEC     200000
#define NETOT   (NE + NEC)
#define NDEPTH  4

#define PAD   136                       // bf16 elems per smem row (272B: conflict-free ldmatrix)
#define WSTR  (128 * PAD * 2)           // bytes per W image in smem (34816)
#define ASTR  (64 * PAD * 2)            // bytes per A image in smem  (17408)
#define SM_TOTAL (4 * WSTR + 2 * ASTR)  // 174080 bytes

// ---------------- scratch (static device globals; no allocation) ----------------
__device__ float g_xw1[N_NODES * DIM];
__device__ float g_xw2[N_NODES * DIM];
__device__ float g_xa [N_NODES * DIM];
__device__ float g_xb [N_NODES * DIM];
__device__ float g_dinv1[N_NODES];      // holds degree during count, then rsqrt(deg)
__device__ float g_dinv2[N_NODES];
__device__ int   g_cnt[N_NODES];        // combined in-degree (CSR row sizes)
__device__ int   g_rowptr[N_NODES + 1];
__device__ int   g_wcur[N_NODES];       // fill cursors
__device__ int   g_blocksum[512];
__device__ int2  g_entry[NETOT];        // {src | flag<<31, norm bits}
__device__ int   g_is64;
// bf16 weight images, transposed [n][k]: [layer][conv_hi, conv_lo, ctrl_hi, ctrl_lo]
__device__ __nv_bfloat16 g_wimg[NDEPTH * 4 * DIM * DIM];

// ---------------- PTX helpers (base sm_103 features only) ----------------
__device__ __forceinline__ uint32_t smem_u32(const void* p) {
    uint32_t a;
    asm("{ .reg .u64 t; cvta.to.shared.u64 t, %1; cvt.u32.u64 %0, t; }" : "=r"(a) : "l"(p));
    return a;
}
__device__ __forceinline__ void ldm4(uint32_t* r, uint32_t addr) {
    asm volatile("ldmatrix.sync.aligned.m8n8.x4.shared.b16 {%0,%1,%2,%3}, [%4];"
                 : "=r"(r[0]), "=r"(r[1]), "=r"(r[2]), "=r"(r[3]) : "r"(addr));
}
__device__ __forceinline__ void mma_bf16(float* d, const uint32_t* a, uint32_t b0, uint32_t b1) {
    asm volatile("mma.sync.aligned.m16n8k16.row.col.f32.bf16.bf16.f32 "
                 "{%0,%1,%2,%3}, {%4,%5,%6,%7}, {%8,%9}, {%0,%1,%2,%3};"
                 : "+f"(d[0]), "+f"(d[1]), "+f"(d[2]), "+f"(d[3])
                 : "r"(a[0]), "r"(a[1]), "r"(a[2]), "r"(a[3]), "r"(b0), "r"(b1));
}

// ---------------- raw edge parse helpers ----------------
__device__ __forceinline__ int edge_val(const void* buf, long long idx) {
    if (g_is64) return (int)((const long long*)buf)[idx];
    return ((const int*)buf)[idx];
}

// ---------------- dtype autodetect: int64 edges have all-zero high words ----------------
__global__ void detect_kernel(const unsigned int* __restrict__ ebuf, int cnt) {
    __shared__ unsigned int acc;
    if (threadIdx.x == 0) acc = 0u;
    __syncthreads();
    unsigned int v = 0u;
    for (int i = threadIdx.x; i < cnt; i += blockDim.x) v |= ebuf[2 * i + 1];
    atomicOr(&acc, v);
    __syncthreads();
    if (threadIdx.x == 0) g_is64 = (acc == 0u) ? 1 : 0;
}

// ---------------- degree init + count (self-loop counts as 1) ----------------
__global__ void init_deg_kernel(int n) {
    int i = blockIdx.x * blockDim.x + threadIdx.x;
    if (i < n) { g_dinv1[i] = 1.0f; g_dinv2[i] = 1.0f; }
}
__global__ void count_deg_kernel(const void* __restrict__ ebuf, const void* __restrict__ cbuf,
                                 int E, int EC) {
    int i = blockIdx.x * blockDim.x + threadIdx.x;
    if (i >= E + EC) return;
    if (i < E) {
        int d = edge_val(ebuf, (long long)E + i);
        atomicAdd(&g_dinv1[d], 1.0f);
    } else {
        int j = i - E;
        int d = edge_val(cbuf, (long long)EC + j);
        atomicAdd(&g_dinv2[d], 1.0f);
    }
}

// ---------------- dinv = rsqrt(deg); cnt = combined indeg; per-block sums ----------------
__global__ void dinv_cnt_kernel(int n) {
    __shared__ int sdata[256];
    int i = blockIdx.x * blockDim.x + threadIdx.x;
    int c = 0;
    if (i < n) {
        float d1 = g_dinv1[i], d2 = g_dinv2[i];
        c = (int)(d1 + d2) - 2;             // exclude the two self-loops
        g_cnt[i] = c;
        g_dinv1[i] = rsqrtf(d1);
        g_dinv2[i] = rsqrtf(d2);
    }
    sdata[threadIdx.x] = c;
    __syncthreads();
    for (int off = 128; off > 0; off >>= 1) {
        if (threadIdx.x < off) sdata[threadIdx.x] += sdata[threadIdx.x + off];
        __syncthreads();
    }
    if (threadIdx.x == 0) g_blocksum[blockIdx.x] = sdata[0];
}

// ---------------- scan block sums (one block; nb <= 512) ----------------
__global__ void scan_blocks_kernel(int nb, int n) {
    __shared__ int s[512];
    int t = threadIdx.x;
    s[t] = (t < nb) ? g_blocksum[t] : 0;
    __syncthreads();
    if (t == 0) {
        int run = 0;
        for (int b = 0; b < nb; b++) { int v = s[b]; s[b] = run; run += v; }
        g_rowptr[n] = run;
    }
    __syncthreads();
    if (t < nb) g_blocksum[t] = s[t];
}

// ---------------- rowptr: block exclusive scan + block offset ----------------
__global__ void rowptr_kernel(int n) {
    __shared__ int s[256];
    int i = blockIdx.x * blockDim.x + threadIdx.x;
    int t = threadIdx.x;
    int v = (i < n) ? g_cnt[i] : 0;
    s[t] = v;
    __syncthreads();
#pragma unroll
    for (int off = 1; off < 256; off <<= 1) {
        int add = (t >= off) ? s[t - off] : 0;
        __syncthreads();
        s[t] += add;
        __syncthreads();
    }
    if (i < n) {
        int excl = s[t] - v + g_blocksum[blockIdx.x];
        g_rowptr[i] = excl;
        g_wcur[i]   = excl;
    }
}

// ---------------- fill CSR entries: {src | flag<<31, norm} ----------------
__global__ void fill_kernel(const void* __restrict__ ebuf, const void* __restrict__ cbuf,
                            int E, int EC) {
    int i = blockIdx.x * blockDim.x + threadIdx.x;
    if (i >= E + EC) return;
    int s, d, flag;
    float nm;
    if (i < E) {
        s = edge_val(ebuf, i);
        d = edge_val(ebuf, (long long)E + i);
        nm = g_dinv1[s] * g_dinv1[d];
        flag = 0;
    } else {
        int j = i - E;
        s = edge_val(cbuf, j);
        d = edge_val(cbuf, (long long)EC + j);
        nm = g_dinv2[s] * g_dinv2[d];
        flag = 1;
    }
    int pos = atomicAdd(&g_wcur[d], 1);
    g_entry[pos] = make_int2(s | (flag << 31), __float_as_int(nm));
}

// ---------------- W prep: fp32 W[k][n] -> bf16 hi/lo transposed Wt[n][k] ----------------
__global__ void prep_w_kernel(const float* __restrict__ Wc, const float* __restrict__ Wt) {
    int m = blockIdx.y;                 // 0..7 : layer*2 + gemm
    int l = m >> 1, g = m & 1;
    const float* W = (g ? Wt : Wc) + l * DIM * DIM;
    int idx = blockIdx.x * 256 + threadIdx.x;     // 0..16383
    int k = idx >> 7, nn = idx & 127;
    float v = W[k * 128 + nn];
    __nv_bfloat16 h  = __float2bfloat16(v);
    __nv_bfloat16 lo = __float2bfloat16(v - __bfloat162float(h));
    __nv_bfloat16* base = g_wimg + (size_t)l * 4 * 16384 + (size_t)(g * 2) * 16384;
    base[nn * 128 + k]         = h;     // hi image
    base[16384 + nn * 128 + k] = lo;    // lo image
}

// ---------------- persistent GEMM (mma.sync bf16 3x split), A-load pipelined ------------
// Writes xw1, xw2 only (self-loop + bias now fused into scatter).
template <int RELU>
__global__ void __launch_bounds__(256, 1)
gemm_mma_kernel(const float* __restrict__ A, const __nv_bfloat16* __restrict__ wimg,
                float* __restrict__ xw1, float* __restrict__ xw2,
                int n, int ntiles) {
    extern __shared__ char sm[];
    const uint32_t sbase = smem_u32(sm);
    const uint32_t Wb   = sbase;
    const uint32_t Ahib = sbase + 4 * WSTR;
    const uint32_t Alob = Ahib + ASTR;

    const int tid  = threadIdx.x;
    const int wid  = tid >> 5;
    const int lane = tid & 31;
    const int warp_m = wid & 1;
    const int warp_n = wid >> 1;
    const int tr  = lane & 7;
    const int sel = lane >> 3;

    for (int i = tid; i < 8192; i += 256) {      // W images -> smem (uint4)
        int arr = i >> 11;
        int rem = i & 2047;
        int row = rem >> 4;
        int ch  = rem & 15;
        uint4 v = *(const uint4*)(wimg + (size_t)arr * 16384 + row * 128 + ch * 8);
        *(uint4*)(sm + arr * WSTR + row * PAD * 2 + ch * 16) = v;
    }

    const uint32_t a_off = (uint32_t)((warp_m * 32 + (sel & 1) * 8 + tr) * PAD + (sel >> 1) * 8) * 2;
    const uint32_t b_off = (uint32_t)((warp_n * 32 + (sel >> 1) * 8 + tr) * PAD + (sel & 1) * 8) * 2;
    const int tq = lane & 3;

    const float4* Ap = (const float4*)A;

    // ---- prefetch first tile into registers ----
    float4 pre[8];
    int tile = blockIdx.x;
    if (tile < ntiles) {
        const int row0 = tile * 64;
#pragma unroll
        for (int j = 0; j < 8; j++) {
            int i = tid + j * 256;
            int row = i >> 5, q = i & 31;
            pre[j] = make_float4(0.f, 0.f, 0.f, 0.f);
            if (row0 + row < n) pre[j] = __ldg(&Ap[(size_t)(row0 + row) * 32 + q]);
        }
    }

    for (; tile < ntiles; tile += gridDim.x) {
        const int row0 = tile * 64;
        __syncthreads();   // previous compute done reading A smem

        // ---- convert prefetched tile -> smem (ReLU + bf16 hi/lo split) ----
#pragma unroll
        for (int j = 0; j < 8; j++) {
            int i = tid + j * 256;
            int row = i >> 5, q = i & 31;
            float4 v = pre[j];
            if (RELU) {
                v.x = fmaxf(v.x, 0.f); v.y = fmaxf(v.y, 0.f);
                v.z = fmaxf(v.z, 0.f); v.w = fmaxf(v.w, 0.f);
            }
            __nv_bfloat16 h0 = __float2bfloat16(v.x), h1 = __float2bfloat16(v.y);
            __nv_bfloat16 h2 = __float2bfloat16(v.z), h3 = __float2bfloat16(v.w);
            __nv_bfloat16 l0 = __float2bfloat16(v.x - __bfloat162float(h0));
            __nv_bfloat16 l1 = __float2bfloat16(v.y - __bfloat162float(h1));
            __nv_bfloat16 l2 = __float2bfloat16(v.z - __bfloat162float(h2));
            __nv_bfloat16 l3 = __float2bfloat16(v.w - __bfloat162float(h3));
            uint2 hw, lw;
            hw.x = (uint32_t)__bfloat16_as_ushort(h0) | ((uint32_t)__bfloat16_as_ushort(h1) << 16);
            hw.y = (uint32_t)__bfloat16_as_ushort(h2) | ((uint32_t)__bfloat16_as_ushort(h3) << 16);
            lw.x = (uint32_t)__bfloat16_as_ushort(l0) | ((uint32_t)__bfloat16_as_ushort(l1) << 16);
            lw.y = (uint32_t)__bfloat16_as_ushort(l2) | ((uint32_t)__bfloat16_as_ushort(l3) << 16);
            uint32_t off = (uint32_t)(row * PAD + q * 4) * 2;
            *(uint2*)(sm + (4 * WSTR) + off)        = hw;
            *(uint2*)(sm + (4 * WSTR) + ASTR + off) = lw;
        }
        __syncthreads();

        // ---- issue next tile's global loads (overlap with mma compute) ----
        int nt = tile + gridDim.x;
        if (nt < ntiles) {
            const int nrow0 = nt * 64;
#pragma unroll
            for (int j = 0; j < 8; j++) {
                int i = tid + j * 256;
                int row = i >> 5, q = i & 31;
                pre[j] = make_float4(0.f, 0.f, 0.f, 0.f);
                if (nrow0 + row < n) pre[j] = __ldg(&Ap[(size_t)(nrow0 + row) * 32 + q]);
            }
        }

        // ---- compute: D1, D2 accumulate over K=128 ----
        float acc1[8][4], acc2[8][4];
#pragma unroll
        for (int t = 0; t < 8; t++)
#pragma unroll
            for (int e = 0; e < 4; e++) { acc1[t][e] = 0.f; acc2[t][e] = 0.f; }

#pragma unroll
        for (int ks = 0; ks < 8; ks++) {
            const uint32_t kb = ks * 32;
            uint32_t ah[2][4], al[2][4];
            ldm4(ah[0], Ahib + a_off + kb);
            ldm4(ah[1], Ahib + a_off + 16 * PAD * 2 + kb);
            ldm4(al[0], Alob + a_off + kb);
            ldm4(al[1], Alob + a_off + 16 * PAD * 2 + kb);
#pragma unroll
            for (int g = 0; g < 2; g++) {
                float (*acc)[4] = g ? acc2 : acc1;
#pragma unroll
                for (int jp = 0; jp < 2; jp++) {
                    uint32_t wh[4], wl[4];
                    uint32_t wb = Wb + (uint32_t)(g * 2) * WSTR + b_off + jp * 16 * PAD * 2 + kb;
                    ldm4(wh, wb);
                    ldm4(wl, wb + WSTR);
#pragma unroll
                    for (int i = 0; i < 2; i++)
#pragma unroll
                        for (int jj = 0; jj < 2; jj++) {
                            float* d = acc[i * 4 + jp * 2 + jj];
                            mma_bf16(d, ah[i], wh[jj * 2], wh[jj * 2 + 1]);
                            mma_bf16(d, ah[i], wl[jj * 2], wl[jj * 2 + 1]);
                            mma_bf16(d, al[i], wh[jj * 2], wh[jj * 2 + 1]);
                        }
                }
            }
        }

        // ---- epilogue: write xw1, xw2 only ----
#pragma unroll
        for (int i = 0; i < 2; i++) {
            int ra = row0 + warp_m * 32 + i * 16 + (lane >> 2);
            int rb = ra + 8;
#pragma unroll
            for (int j = 0; j < 4; j++) {
                int t = i * 4 + j;
                int c = warp_n * 32 + j * 8 + tq * 2;
                if (ra < n) {
                    size_t o = (size_t)ra * 128 + c;
                    *(float2*)&xw1[o] = make_float2(acc1[t][0], acc1[t][1]);
                    *(float2*)&xw2[o] = make_float2(acc2[t][0], acc2[t][1]);
                }
                if (rb < n) {
                    size_t o = (size_t)rb * 128 + c;
                    *(float2*)&xw1[o] = make_float2(acc1[t][2], acc1[t][3]);
                    *(float2*)&xw2[o] = make_float2(acc2[t][2], acc2[t][3]);
                }
            }
        }
    }
}

// ---------------- CSR scatter: warp/node, no atomics, self-loop + bias fused ------------
// nxt[v] = xw1[v]*dinv1^2 + xw2[v]*dinv2^2 + b1 + b2 + sum_in-edges.
__global__ void __launch_bounds__(256)
scatter_csr_kernel(float* __restrict__ nxt,
                   const float* __restrict__ xw1, const float* __restrict__ xw2,
                   const int* __restrict__ rowptr, const int2* __restrict__ entry,
                   const float* __restrict__ dinv1, const float* __restrict__ dinv2,
                   const float* __restrict__ b1, const float* __restrict__ b2, int n) {
    int v    = (blockIdx.x * blockDim.x + threadIdx.x) >> 5;
    int lane = threadIdx.x & 31;
    if (v >= n) return;
    int e0 = rowptr[v];
    int e1 = rowptr[v + 1];

    float s1 = dinv1[v]; s1 *= s1;
    float s2 = dinv2[v]; s2 *= s2;
    float4 x1  = __ldg(&((const float4*)(xw1 + (size_t)v * 128))[lane]);
    float4 x2  = __ldg(&((const float4*)(xw2 + (size_t)v * 128))[lane]);
    float4 bb1 = __ldg(&((const float4*)b1)[lane]);
    float4 bb2 = __ldg(&((const float4*)b2)[lane]);
    float4 acc;
    acc.x = x1.x * s1 + x2.x * s2 + bb1.x + bb2.x;
    acc.y = x1.y * s1 + x2.y * s2 + bb1.y + bb2.y;
    acc.z = x1.z * s1 + x2.z * s2 + bb1.z + bb2.z;
    acc.w = x1.w * s1 + x2.w * s2 + bb1.w + bb2.w;

    int e = e0;
    for (; e + 3 < e1; e += 4) {
        int2 ea = __ldg(&entry[e]);
        int2 eb = __ldg(&entry[e + 1]);
        int2 ec = __ldg(&entry[e + 2]);
        int2 ed = __ldg(&entry[e + 3]);
        const float* ba = (ea.x < 0) ? xw2 : xw1;
        const float* bb = (eb.x < 0) ? xw2 : xw1;
        const float* bc = (ec.x < 0) ? xw2 : xw1;
        const float* bd = (ed.x < 0) ? xw2 : xw1;
        float4 va = __ldg(&((const float4*)(ba + (size_t)(ea.x & 0x7FFFFFFF) * 128))[lane]);
        float4 vb = __ldg(&((const float4*)(bb + (size_t)(eb.x & 0x7FFFFFFF) * 128))[lane]);
        float4 vc = __ldg(&((const float4*)(bc + (size_t)(ec.x & 0x7FFFFFFF) * 128))[lane]);
        float4 vd = __ldg(&((const float4*)(bd + (size_t)(ed.x & 0x7FFFFFFF) * 128))[lane]);
        float wa = __int_as_float(ea.y), wb2 = __int_as_float(eb.y);
        float wc = __int_as_float(ec.y), wd  = __int_as_float(ed.y);
        acc.x += va.x * wa; acc.y += va.y * wa; acc.z += va.z * wa; acc.w += va.w * wa;
        acc.x += vb.x * wb2; acc.y += vb.y * wb2; acc.z += vb.z * wb2; acc.w += vb.w * wb2;
        acc.x += vc.x * wc; acc.y += vc.y * wc; acc.z += vc.z * wc; acc.w += vc.w * wc;
        acc.x += vd.x * wd; acc.y += vd.y * wd; acc.z += vd.z * wd; acc.w += vd.w * wd;
    }
    for (; e < e1; e++) {
        int2 ea = __ldg(&entry[e]);
        const float* ba = (ea.x < 0) ? xw2 : xw1;
        float wa = __int_as_float(ea.y);
        float4 va = __ldg(&((const float4*)(ba + (size_t)(ea.x & 0x7FFFFFFF) * 128))[lane]);
        acc.x += va.x * wa; acc.y += va.y * wa; acc.z += va.z * wa; acc.w += va.w * wa;
    }
    ((float4*)(nxt + (size_t)v * 128))[lane] = acc;
}

// ---------------- host ----------------
extern "C" void kernel_launch(void* const* d_in, const int* in_sizes, int n_in,
                              void* d_out, int out_size) {
    const float* x  = (const float*)d_in[0];
    const void*  ei = d_in[1];
    const void*  ci = d_in[2];
    const float* Wc = (const float*)d_in[3];
    const float* bc = (const float*)d_in[4];
    const float* Wt = (const float*)d_in[5];
    const float* bt = (const float*)d_in[6];

    const int n  = in_sizes[0] / DIM;   // 100000
    const int E  = in_sizes[1] / 2;     // 600000
    const int EC = in_sizes[2] / 2;     // 200000

    float *xw1, *xw2, *xa, *xb, *dinv1, *dinv2;
    int *rowptr; int2 *entry;
    __nv_bfloat16* wimg;
    cudaGetSymbolAddress((void**)&xw1,   g_xw1);
    cudaGetSymbolAddress((void**)&xw2,   g_xw2);
    cudaGetSymbolAddress((void**)&xa,    g_xa);
    cudaGetSymbolAddress((void**)&xb,    g_xb);
    cudaGetSymbolAddress((void**)&dinv1, g_dinv1);
    cudaGetSymbolAddress((void**)&dinv2, g_dinv2);
    cudaGetSymbolAddress((void**)&rowptr,g_rowptr);
    cudaGetSymbolAddress((void**)&entry, g_entry);
    cudaGetSymbolAddress((void**)&wimg,  g_wimg);

    cudaFuncSetAttribute(gemm_mma_kernel<0>, cudaFuncAttributeMaxDynamicSharedMemorySize, SM_TOTAL);
    cudaFuncSetAttribute(gemm_mma_kernel<1>, cudaFuncAttributeMaxDynamicSharedMemorySize, SM_TOTAL);

    const int nb = (n + 255) / 256;     // 391 blocks

    // --- precompute: degrees, dinv, CSR (once; reused by all layers) ---
    int chk = E < 65536 ? E : 65536;
    detect_kernel<<<1, 256>>>((const unsigned int*)ei, chk);
    init_deg_kernel<<<nb, 256>>>(n);
    count_deg_kernel<<<(E + EC + 255) / 256, 256>>>(ei, ci, E, EC);
    dinv_cnt_kernel<<<nb, 256>>>(n);
    scan_blocks_kernel<<<1, 512>>>(nb, n);
    rowptr_kernel<<<nb, 256>>>(n);
    fill_kernel<<<(E + EC + 255) / 256, 256>>>(ei, ci, E, EC);
    {
        dim3 pw(64, 8);
        prep_w_kernel<<<pw, 256>>>(Wc, Wt);
    }

    // --- 4 layers ---
    const int ntiles = (n + 63) / 64;
    const int gblocks = 148;
    const float* cur = x;
    for (int i = 0; i < NDEPTH; i++) {
        float* nxt = (i == NDEPTH - 1) ? (float*)d_out : ((i & 1) ? xb : xa);
        const __nv_bfloat16* wl = wimg + (size_t)i * 4 * 16384;
        if (i == 0)
            gemm_mma_kernel<0><<<gblocks, 256, SM_TOTAL>>>(cur, wl, xw1, xw2, n, ntiles);
        else
            gemm_mma_kernel<1><<<gblocks, 256, SM_TOTAL>>>(cur, wl, xw1, xw2, n, ntiles);

        scatter_csr_kernel<<<(n * 32 + 255) / 256, 256>>>(nxt, xw1, xw2, rowptr, entry,
                                                          dinv1, dinv2,
                                                          bc + (size_t)i * DIM, bt + (size_t)i * DIM, n);
        cur = nxt;
    }
}

// round 8
// speedup vs baseline: 3.7223x; 1.1932x over previous
#include <cuda_runtime.h>
#include <cuda_bf16.h>
#include <cuda_fp16.h>
#include <cstdint>

#define N_NODES 100000
#define DIM     128
#define NE      600000
#define NEC     200000
#define NETOT   (NE + NEC)
#define NDEPTH  4

#define PAD   136                       // bf16 elems per smem row (272B: conflict-free ldmatrix)
#define WSTR  (128 * PAD * 2)           // bytes per W image in smem (34816)
#define ASTR  (64 * PAD * 2)            // bytes per A image in smem  (17408)
#define SM_TOTAL (4 * WSTR + 2 * ASTR)  // 174080 bytes

// ---------------- scratch (static device globals; no allocation) ----------------
__device__ __half g_xw1[N_NODES * DIM];   // fp16 message buffers (fp32 accum elsewhere)
__device__ __half g_xw2[N_NODES * DIM];
__device__ float g_xa [N_NODES * DIM];
__device__ float g_xb [N_NODES * DIM];
__device__ float g_dinv1[N_NODES];      // holds degree during count, then rsqrt(deg)
__device__ float g_dinv2[N_NODES];
__device__ int   g_cnt[N_NODES];        // combined in-degree (CSR row sizes)
__device__ int   g_rowptr[N_NODES + 1];
__device__ int   g_wcur[N_NODES];       // fill cursors
__device__ int   g_blocksum[512];
__device__ int2  g_entry[NETOT];        // {src | flag<<31, norm bits}
__device__ int   g_is64;
// bf16 weight images, transposed [n][k]: [layer][conv_hi, conv_lo, ctrl_hi, ctrl_lo]
__device__ __nv_bfloat16 g_wimg[NDEPTH * 4 * DIM * DIM];

// ---------------- PTX helpers (base sm_103 features only) ----------------
__device__ __forceinline__ uint32_t smem_u32(const void* p) {
    uint32_t a;
    asm("{ .reg .u64 t; cvta.to.shared.u64 t, %1; cvt.u32.u64 %0, t; }" : "=r"(a) : "l"(p));
    return a;
}
__device__ __forceinline__ void ldm4(uint32_t* r, uint32_t addr) {
    asm volatile("ldmatrix.sync.aligned.m8n8.x4.shared.b16 {%0,%1,%2,%3}, [%4];"
                 : "=r"(r[0]), "=r"(r[1]), "=r"(r[2]), "=r"(r[3]) : "r"(addr));
}
__device__ __forceinline__ void mma_bf16(float* d, const uint32_t* a, uint32_t b0, uint32_t b1) {
    asm volatile("mma.sync.aligned.m16n8k16.row.col.f32.bf16.bf16.f32 "
                 "{%0,%1,%2,%3}, {%4,%5,%6,%7}, {%8,%9}, {%0,%1,%2,%3};"
                 : "+f"(d[0]), "+f"(d[1]), "+f"(d[2]), "+f"(d[3])
                 : "r"(a[0]), "r"(a[1]), "r"(a[2]), "r"(a[3]), "r"(b0), "r"(b1));
}

// ---------------- raw edge parse helpers ----------------
__device__ __forceinline__ int edge_val(const void* buf, long long idx) {
    if (g_is64) return (int)((const long long*)buf)[idx];
    return ((const int*)buf)[idx];
}

// ---------------- dtype autodetect: int64 edges have all-zero high words ----------------
__global__ void detect_kernel(const unsigned int* __restrict__ ebuf, int cnt) {
    __shared__ unsigned int acc;
    if (threadIdx.x == 0) acc = 0u;
    __syncthreads();
    unsigned int v = 0u;
    for (int i = threadIdx.x; i < cnt; i += blockDim.x) v |= ebuf[2 * i + 1];
    atomicOr(&acc, v);
    __syncthreads();
    if (threadIdx.x == 0) g_is64 = (acc == 0u) ? 1 : 0;
}

// ---------------- degree init + count (self-loop counts as 1) ----------------
__global__ void init_deg_kernel(int n) {
    int i = blockIdx.x * blockDim.x + threadIdx.x;
    if (i < n) { g_dinv1[i] = 1.0f; g_dinv2[i] = 1.0f; }
}
__global__ void count_deg_kernel(const void* __restrict__ ebuf, const void* __restrict__ cbuf,
                                 int E, int EC) {
    int i = blockIdx.x * blockDim.x + threadIdx.x;
    if (i >= E + EC) return;
    if (i < E) {
        int d = edge_val(ebuf, (long long)E + i);
        atomicAdd(&g_dinv1[d], 1.0f);
    } else {
        int j = i - E;
        int d = edge_val(cbuf, (long long)EC + j);
        atomicAdd(&g_dinv2[d], 1.0f);
    }
}

// ---------------- dinv = rsqrt(deg); cnt = combined indeg; per-block sums ----------------
__global__ void dinv_cnt_kernel(int n) {
    __shared__ int sdata[256];
    int i = blockIdx.x * blockDim.x + threadIdx.x;
    int c = 0;
    if (i < n) {
        float d1 = g_dinv1[i], d2 = g_dinv2[i];
        c = (int)(d1 + d2) - 2;             // exclude the two self-loops
        g_cnt[i] = c;
        g_dinv1[i] = rsqrtf(d1);
        g_dinv2[i] = rsqrtf(d2);
    }
    sdata[threadIdx.x] = c;
    __syncthreads();
    for (int off = 128; off > 0; off >>= 1) {
        if (threadIdx.x < off) sdata[threadIdx.x] += sdata[threadIdx.x + off];
        __syncthreads();
    }
    if (threadIdx.x == 0) g_blocksum[blockIdx.x] = sdata[0];
}

// ---------------- scan block sums (one block; nb <= 512) ----------------
__global__ void scan_blocks_kernel(int nb, int n) {
    __shared__ int s[512];
    int t = threadIdx.x;
    s[t] = (t < nb) ? g_blocksum[t] : 0;
    __syncthreads();
    if (t == 0) {
        int run = 0;
        for (int b = 0; b < nb; b++) { int v = s[b]; s[b] = run; run += v; }
        g_rowptr[n] = run;
    }
    __syncthreads();
    if (t < nb) g_blocksum[t] = s[t];
}

// ---------------- rowptr: block exclusive scan + block offset ----------------
__global__ void rowptr_kernel(int n) {
    __shared__ int s[256];
    int i = blockIdx.x * blockDim.x + threadIdx.x;
    int t = threadIdx.x;
    int v = (i < n) ? g_cnt[i] : 0;
    s[t] = v;
    __syncthreads();
#pragma unroll
    for (int off = 1; off < 256; off <<= 1) {
        int add = (t >= off) ? s[t - off] : 0;
        __syncthreads();
        s[t] += add;
        __syncthreads();
    }
    if (i < n) {
        int excl = s[t] - v + g_blocksum[blockIdx.x];
        g_rowptr[i] = excl;
        g_wcur[i]   = excl;
    }
}

// ---------------- fill CSR entries: {src | flag<<31, norm} ----------------
__global__ void fill_kernel(const void* __restrict__ ebuf, const void* __restrict__ cbuf,
                            int E, int EC) {
    int i = blockIdx.x * blockDim.x + threadIdx.x;
    if (i >= E + EC) return;
    int s, d, flag;
    float nm;
    if (i < E) {
        s = edge_val(ebuf, i);
        d = edge_val(ebuf, (long long)E + i);
        nm = g_dinv1[s] * g_dinv1[d];
        flag = 0;
    } else {
        int j = i - E;
        s = edge_val(cbuf, j);
        d = edge_val(cbuf, (long long)EC + j);
        nm = g_dinv2[s] * g_dinv2[d];
        flag = 1;
    }
    int pos = atomicAdd(&g_wcur[d], 1);
    g_entry[pos] = make_int2(s | (flag << 31), __float_as_int(nm));
}

// ---------------- W prep: fp32 W[k][n] -> bf16 hi/lo transposed Wt[n][k] ----------------
__global__ void prep_w_kernel(const float* __restrict__ Wc, const float* __restrict__ Wt) {
    int m = blockIdx.y;                 // 0..7 : layer*2 + gemm
    int l = m >> 1, g = m & 1;
    const float* W = (g ? Wt : Wc) + l * DIM * DIM;
    int idx = blockIdx.x * 256 + threadIdx.x;     // 0..16383
    int k = idx >> 7, nn = idx & 127;
    float v = W[k * 128 + nn];
    __nv_bfloat16 h  = __float2bfloat16(v);
    __nv_bfloat16 lo = __float2bfloat16(v - __bfloat162float(h));
    __nv_bfloat16* base = g_wimg + (size_t)l * 4 * 16384 + (size_t)(g * 2) * 16384;
    base[nn * 128 + k]         = h;     // hi image
    base[16384 + nn * 128 + k] = lo;    // lo image
}

// ---------------- persistent GEMM (mma.sync bf16 3x split), A-load pipelined ------------
// Writes xw1, xw2 as fp16 message buffers (self-loop + bias fused into scatter).
template <int RELU>
__global__ void __launch_bounds__(256, 1)
gemm_mma_kernel(const float* __restrict__ A, const __nv_bfloat16* __restrict__ wimg,
                __half* __restrict__ xw1, __half* __restrict__ xw2,
                int n, int ntiles) {
    extern __shared__ char sm[];
    const uint32_t sbase = smem_u32(sm);
    const uint32_t Wb   = sbase;
    const uint32_t Ahib = sbase + 4 * WSTR;
    const uint32_t Alob = Ahib + ASTR;

    const int tid  = threadIdx.x;
    const int wid  = tid >> 5;
    const int lane = tid & 31;
    const int warp_m = wid & 1;
    const int warp_n = wid >> 1;
    const int tr  = lane & 7;
    const int sel = lane >> 3;

    for (int i = tid; i < 8192; i += 256) {      // W images -> smem (uint4)
        int arr = i >> 11;
        int rem = i & 2047;
        int row = rem >> 4;
        int ch  = rem & 15;
        uint4 v = *(const uint4*)(wimg + (size_t)arr * 16384 + row * 128 + ch * 8);
        *(uint4*)(sm + arr * WSTR + row * PAD * 2 + ch * 16) = v;
    }

    const uint32_t a_off = (uint32_t)((warp_m * 32 + (sel & 1) * 8 + tr) * PAD + (sel >> 1) * 8) * 2;
    const uint32_t b_off = (uint32_t)((warp_n * 32 + (sel >> 1) * 8 + tr) * PAD + (sel & 1) * 8) * 2;
    const int tq = lane & 3;

    const float4* Ap = (const float4*)A;

    // ---- prefetch first tile into registers ----
    float4 pre[8];
    int tile = blockIdx.x;
    if (tile < ntiles) {
        const int row0 = tile * 64;
#pragma unroll
        for (int j = 0; j < 8; j++) {
            int i = tid + j * 256;
            int row = i >> 5, q = i & 31;
            pre[j] = make_float4(0.f, 0.f, 0.f, 0.f);
            if (row0 + row < n) pre[j] = __ldg(&Ap[(size_t)(row0 + row) * 32 + q]);
        }
    }

    for (; tile < ntiles; tile += gridDim.x) {
        const int row0 = tile * 64;
        __syncthreads();   // previous compute done reading A smem

        // ---- convert prefetched tile -> smem (ReLU + bf16 hi/lo split) ----
#pragma unroll
        for (int j = 0; j < 8; j++) {
            int i = tid + j * 256;
            int row = i >> 5, q = i & 31;
            float4 v = pre[j];
            if (RELU) {
                v.x = fmaxf(v.x, 0.f); v.y = fmaxf(v.y, 0.f);
                v.z = fmaxf(v.z, 0.f); v.w = fmaxf(v.w, 0.f);
            }
            __nv_bfloat16 h0 = __float2bfloat16(v.x), h1 = __float2bfloat16(v.y);
            __nv_bfloat16 h2 = __float2bfloat16(v.z), h3 = __float2bfloat16(v.w);
            __nv_bfloat16 l0 = __float2bfloat16(v.x - __bfloat162float(h0));
            __nv_bfloat16 l1 = __float2bfloat16(v.y - __bfloat162float(h1));
            __nv_bfloat16 l2 = __float2bfloat16(v.z - __bfloat162float(h2));
            __nv_bfloat16 l3 = __float2bfloat16(v.w - __bfloat162float(h3));
            uint2 hw, lw;
            hw.x = (uint32_t)__bfloat16_as_ushort(h0) | ((uint32_t)__bfloat16_as_ushort(h1) << 16);
            hw.y = (uint32_t)__bfloat16_as_ushort(h2) | ((uint32_t)__bfloat16_as_ushort(h3) << 16);
            lw.x = (uint32_t)__bfloat16_as_ushort(l0) | ((uint32_t)__bfloat16_as_ushort(l1) << 16);
            lw.y = (uint32_t)__bfloat16_as_ushort(l2) | ((uint32_t)__bfloat16_as_ushort(l3) << 16);
            uint32_t off = (uint32_t)(row * PAD + q * 4) * 2;
            *(uint2*)(sm + (4 * WSTR) + off)        = hw;
            *(uint2*)(sm + (4 * WSTR) + ASTR + off) = lw;
        }
        __syncthreads();

        // ---- issue next tile's global loads (overlap with mma compute) ----
        int nt = tile + gridDim.x;
        if (nt < ntiles) {
            const int nrow0 = nt * 64;
#pragma unroll
            for (int j = 0; j < 8; j++) {
                int i = tid + j * 256;
                int row = i >> 5, q = i & 31;
                pre[j] = make_float4(0.f, 0.f, 0.f, 0.f);
                if (nrow0 + row < n) pre[j] = __ldg(&Ap[(size_t)(nrow0 + row) * 32 + q]);
            }
        }

        // ---- compute: D1, D2 accumulate over K=128 ----
        float acc1[8][4], acc2[8][4];
#pragma unroll
        for (int t = 0; t < 8; t++)
#pragma unroll
            for (int e = 0; e < 4; e++) { acc1[t][e] = 0.f; acc2[t][e] = 0.f; }

#pragma unroll
        for (int ks = 0; ks < 8; ks++) {
            const uint32_t kb = ks * 32;
            uint32_t ah[2][4], al[2][4];
            ldm4(ah[0], Ahib + a_off + kb);
            ldm4(ah[1], Ahib + a_off + 16 * PAD * 2 + kb);
            ldm4(al[0], Alob + a_off + kb);
            ldm4(al[1], Alob + a_off + 16 * PAD * 2 + kb);
#pragma unroll
            for (int g = 0; g < 2; g++) {
                float (*acc)[4] = g ? acc2 : acc1;
#pragma unroll
                for (int jp = 0; jp < 2; jp++) {
                    uint32_t wh[4], wl[4];
                    uint32_t wb = Wb + (uint32_t)(g * 2) * WSTR + b_off + jp * 16 * PAD * 2 + kb;
                    ldm4(wh, wb);
                    ldm4(wl, wb + WSTR);
#pragma unroll
                    for (int i = 0; i < 2; i++)
#pragma unroll
                        for (int jj = 0; jj < 2; jj++) {
                            float* d = acc[i * 4 + jp * 2 + jj];
                            mma_bf16(d, ah[i], wh[jj * 2], wh[jj * 2 + 1]);
                            mma_bf16(d, ah[i], wl[jj * 2], wl[jj * 2 + 1]);
                            mma_bf16(d, al[i], wh[jj * 2], wh[jj * 2 + 1]);
                        }
                }
            }
        }

        // ---- epilogue: write xw1, xw2 as fp16 ----
#pragma unroll
        for (int i = 0; i < 2; i++) {
            int ra = row0 + warp_m * 32 + i * 16 + (lane >> 2);
            int rb = ra + 8;
#pragma unroll
            for (int j = 0; j < 4; j++) {
                int t = i * 4 + j;
                int c = warp_n * 32 + j * 8 + tq * 2;
                if (ra < n) {
                    size_t o = (size_t)ra * 128 + c;
                    *(__half2*)&xw1[o] = __floats2half2_rn(acc1[t][0], acc1[t][1]);
                    *(__half2*)&xw2[o] = __floats2half2_rn(acc2[t][0], acc2[t][1]);
                }
                if (rb < n) {
                    size_t o = (size_t)rb * 128 + c;
                    *(__half2*)&xw1[o] = __floats2half2_rn(acc1[t][2], acc1[t][3]);
                    *(__half2*)&xw2[o] = __floats2half2_rn(acc2[t][2], acc2[t][3]);
                }
            }
        }
    }
}

// ---------------- CSR scatter: warp/node, no atomics, fp16 gather, fp32 accum -----------
// nxt[v] = xw1[v]*dinv1^2 + xw2[v]*dinv2^2 + b1 + b2 + sum_in-edges.
__device__ __forceinline__ void acc_half4(float4& acc, uint2 raw, float w) {
    float2 p0 = __half22float2(*(__half2*)&raw.x);
    float2 p1 = __half22float2(*(__half2*)&raw.y);
    acc.x += p0.x * w; acc.y += p0.y * w; acc.z += p1.x * w; acc.w += p1.y * w;
}

__global__ void __launch_bounds__(256)
scatter_csr_kernel(float* __restrict__ nxt,
                   const __half* __restrict__ xw1, const __half* __restrict__ xw2,
                   const int* __restrict__ rowptr, const int2* __restrict__ entry,
                   const float* __restrict__ dinv1, const float* __restrict__ dinv2,
                   const float* __restrict__ b1, const float* __restrict__ b2, int n) {
    int v    = (blockIdx.x * blockDim.x + threadIdx.x) >> 5;
    int lane = threadIdx.x & 31;
    if (v >= n) return;
    int e0 = rowptr[v];
    int e1 = rowptr[v + 1];

    float s1 = dinv1[v]; s1 *= s1;
    float s2 = dinv2[v]; s2 *= s2;
    uint2 sr1 = __ldg(&((const uint2*)(xw1 + (size_t)v * 128))[lane]);
    uint2 sr2 = __ldg(&((const uint2*)(xw2 + (size_t)v * 128))[lane]);
    float4 bb1 = __ldg(&((const float4*)b1)[lane]);
    float4 bb2 = __ldg(&((const float4*)b2)[lane]);
    float4 acc = make_float4(bb1.x + bb2.x, bb1.y + bb2.y, bb1.z + bb2.z, bb1.w + bb2.w);
    acc_half4(acc, sr1, s1);
    acc_half4(acc, sr2, s2);

    int e = e0;
    for (; e + 3 < e1; e += 4) {
        int2 ea = __ldg(&entry[e]);
        int2 eb = __ldg(&entry[e + 1]);
        int2 ec = __ldg(&entry[e + 2]);
        int2 ed = __ldg(&entry[e + 3]);
        const __half* ba = (ea.x < 0) ? xw2 : xw1;
        const __half* bb = (eb.x < 0) ? xw2 : xw1;
        const __half* bc = (ec.x < 0) ? xw2 : xw1;
        const __half* bd = (ed.x < 0) ? xw2 : xw1;
        uint2 va = __ldg(&((const uint2*)(ba + (size_t)(ea.x & 0x7FFFFFFF) * 128))[lane]);
        uint2 vb = __ldg(&((const uint2*)(bb + (size_t)(eb.x & 0x7FFFFFFF) * 128))[lane]);
        uint2 vc = __ldg(&((const uint2*)(bc + (size_t)(ec.x & 0x7FFFFFFF) * 128))[lane]);
        uint2 vd = __ldg(&((const uint2*)(bd + (size_t)(ed.x & 0x7FFFFFFF) * 128))[lane]);
        acc_half4(acc, va, __int_as_float(ea.y));
        acc_half4(acc, vb, __int_as_float(eb.y));
        acc_half4(acc, vc, __int_as_float(ec.y));
        acc_half4(acc, vd, __int_as_float(ed.y));
    }
    for (; e < e1; e++) {
        int2 ea = __ldg(&entry[e]);
        const __half* ba = (ea.x < 0) ? xw2 : xw1;
        uint2 va = __ldg(&((const uint2*)(ba + (size_t)(ea.x & 0x7FFFFFFF) * 128))[lane]);
        acc_half4(acc, va, __int_as_float(ea.y));
    }
    ((float4*)(nxt + (size_t)v * 128))[lane] = acc;
}

// ---------------- host ----------------
extern "C" void kernel_launch(void* const* d_in, const int* in_sizes, int n_in,
                              void* d_out, int out_size) {
    const float* x  = (const float*)d_in[0];
    const void*  ei = d_in[1];
    const void*  ci = d_in[2];
    const float* Wc = (const float*)d_in[3];
    const float* bc = (const float*)d_in[4];
    const float* Wt = (const float*)d_in[5];
    const float* bt = (const float*)d_in[6];

    const int n  = in_sizes[0] / DIM;   // 100000
    const int E  = in_sizes[1] / 2;     // 600000
    const int EC = in_sizes[2] / 2;     // 200000

    float *xa, *xb, *dinv1, *dinv2;
    __half *xw1, *xw2;
    int *rowptr; int2 *entry;
    __nv_bfloat16* wimg;
    cudaGetSymbolAddress((void**)&xw1,   g_xw1);
    cudaGetSymbolAddress((void**)&xw2,   g_xw2);
    cudaGetSymbolAddress((void**)&xa,    g_xa);
    cudaGetSymbolAddress((void**)&xb,    g_xb);
    cudaGetSymbolAddress((void**)&dinv1, g_dinv1);
    cudaGetSymbolAddress((void**)&dinv2, g_dinv2);
    cudaGetSymbolAddress((void**)&rowptr,g_rowptr);
    cudaGetSymbolAddress((void**)&entry, g_entry);
    cudaGetSymbolAddress((void**)&wimg,  g_wimg);

    cudaFuncSetAttribute(gemm_mma_kernel<0>, cudaFuncAttributeMaxDynamicSharedMemorySize, SM_TOTAL);
    cudaFuncSetAttribute(gemm_mma_kernel<1>, cudaFuncAttributeMaxDynamicSharedMemorySize, SM_TOTAL);

    const int nb = (n + 255) / 256;     // 391 blocks

    // --- precompute: degrees, dinv, CSR (once; reused by all layers) ---
    int chk = E < 65536 ? E : 65536;
    detect_kernel<<<1, 256>>>((const unsigned int*)ei, chk);
    init_deg_kernel<<<nb, 256>>>(n);
    count_deg_kernel<<<(E + EC + 255) / 256, 256>>>(ei, ci, E, EC);
    dinv_cnt_kernel<<<nb, 256>>>(n);
    scan_blocks_kernel<<<1, 512>>>(nb, n);
    rowptr_kernel<<<nb, 256>>>(n);
    fill_kernel<<<(E + EC + 255) / 256, 256>>>(ei, ci, E, EC);
    {
        dim3 pw(64, 8);
        prep_w_kernel<<<pw, 256>>>(Wc, Wt);
    }

    // --- 4 layers ---
    const int ntiles = (n + 63) / 64;
    const int gblocks = 148;
    const float* cur = x;
    for (int i = 0; i < NDEPTH; i++) {
        float* nxt = (i == NDEPTH - 1) ? (float*)d_out : ((i & 1) ? xb : xa);
        const __nv_bfloat16* wl = wimg + (size_t)i * 4 * 16384;
        if (i == 0)
            gemm_mma_kernel<0><<<gblocks, 256, SM_TOTAL>>>(cur, wl, xw1, xw2, n, ntiles);
        else
            gemm_mma_kernel<1><<<gblocks, 256, SM_TOTAL>>>(cur, wl, xw1, xw2, n, ntiles);

        scatter_csr_kernel<<<(n * 32 + 255) / 256, 256>>>(nxt, xw1, xw2, rowptr, entry,
                                                          dinv1, dinv2,
                                                          bc + (size_t)i * DIM, bt + (size_t)i * DIM, n);
        cur = nxt;
    }
}